// round 11
// baseline (speedup 1.0000x reference)
#include <cuda_runtime.h>
#include <cuda_fp16.h>
#include <cstdint>

#define N_NODES 50000
#define N_EDGES 1600000
#define F_DIM 32
#define H_DIM 128
#define HID 512
#define OUTD 256

// Scratch (__device__ globals = allocation-guard-legal scratch)
__device__ __align__(16) __half g_PdstH[(size_t)N_NODES * HID];
__device__ __align__(16) __half g_PsrcH[(size_t)N_NODES * HID];
// fp16 weights, B-fragment u2 {(k0,k0+1),(k0+8,k0+9)} with quad-reordered cols:
// row R (0..127): slice=R>>2, tg=R&3, k0=slice*16+2*tg.
// u2 index u within row: c = (u>>4)*16 + (u&1)*8 + ((u>>1)&7)
// so uint4 slot q holds cols {(q>>3)*16+(q&7), +8}.
__device__ __align__(16) uint2 g_W2q[(size_t)128 * 512];
__device__ __align__(16) uint2 g_W3q[(size_t)128 * 256];

__device__ __forceinline__ uint32_t smem_u32(const void* p) {
    uint32_t a;
    asm("{ .reg .u64 t; cvta.to.shared.u64 t, %1; cvt.u32.u64 %0, t; }" : "=r"(a) : "l"(p));
    return a;
}
__device__ __forceinline__ void mma16(float* d, const uint32_t* a,
                                      uint32_t b0, uint32_t b1) {
    asm volatile(
        "mma.sync.aligned.m16n8k16.row.col.f32.f16.f16.f32 "
        "{%0,%1,%2,%3},{%4,%5,%6,%7},{%8,%9},{%0,%1,%2,%3};"
        : "+f"(d[0]), "+f"(d[1]), "+f"(d[2]), "+f"(d[3])
        : "r"(a[0]), "r"(a[1]), "r"(a[2]), "r"(a[3]), "r"(b0), "r"(b1));
}
#define LDSM4(r, addr) \
    asm volatile("ldmatrix.sync.aligned.m8n8.x4.shared.b16 {%0,%1,%2,%3}, [%4];" \
        : "=r"((r)[0]), "=r"((r)[1]), "=r"((r)[2]), "=r"((r)[3]) : "r"(addr))
__device__ __forceinline__ uint32_t pack2(float x, float y) {
    __half2 h = __floats2half2_rn(x, y);
    return *(uint32_t*)&h;
}
__device__ __forceinline__ uint32_t h1op(uint32_t a, uint32_t b, uint32_t w,
                                         __half2 d2) {
    __half2 r = __hfma2(d2, *(__half2*)&w,
                        __hadd2(*(__half2*)&a, *(__half2*)&b));
    r = __hmax2(r, __floats2half2_rn(0.f, 0.f));
    return *(uint32_t*)&r;
}
#define CP16(sa, gp) asm volatile("cp.async.cg.shared.global [%0], [%1], 16;" :: "r"(sa), "l"(gp) : "memory")
#define CP_COMMIT() asm volatile("cp.async.commit_group;" ::: "memory")
#define CP_WAIT0()  asm volatile("cp.async.wait_group 0;" ::: "memory")

// ---------------------------------------------------------------------------
// Kernel 1: per-node layer-1 precompute (R9 version, proven).
// ---------------------------------------------------------------------------
__global__ __launch_bounds__(512) void node_pre_kernel(
    const float* __restrict__ nf, const float* __restrict__ nh,
    const float* __restrict__ W1, const float* __restrict__ b1) {
    __shared__ float fs[160 * 68];
    const int nb = blockIdx.x * 64, tid = threadIdx.x;
    for (int idx = tid; idx < 64 * 160; idx += 512) {
        int k = idx >> 6, m = idx & 63, n = nb + m;
        float v = 0.f;
        if (n < N_NODES)
            v = (k < F_DIM) ? nf[(size_t)n * F_DIM + k] : nh[(size_t)n * H_DIM + (k - F_DIM)];
        fs[k * 68 + m] = v;
    }
    __syncthreads();
    const int j = tid;
    float acc[64];
    const float bj = b1[j];
#pragma unroll
    for (int m = 0; m < 64; m++) acc[m] = bj;
    for (int k = 0; k < F_DIM; k++) {
        float w = __ldg(W1 + (size_t)k * HID + j);
        const float4* f4 = (const float4*)(fs + k * 68);
#pragma unroll
        for (int mq = 0; mq < 16; mq++) {
            float4 f = f4[mq];
            acc[4 * mq + 0] += f.x * w; acc[4 * mq + 1] += f.y * w;
            acc[4 * mq + 2] += f.z * w; acc[4 * mq + 3] += f.w * w;
        }
    }
    for (int h = 0; h < H_DIM; h++) {
        float w = __ldg(W1 + (size_t)(32 + h) * HID + j) +
                  __ldg(W1 + (size_t)(192 + h) * HID + j);
        const float4* f4 = (const float4*)(fs + (32 + h) * 68);
#pragma unroll
        for (int mq = 0; mq < 16; mq++) {
            float4 f = f4[mq];
            acc[4 * mq + 0] += f.x * w; acc[4 * mq + 1] += f.y * w;
            acc[4 * mq + 2] += f.z * w; acc[4 * mq + 3] += f.w * w;
        }
    }
    for (int m = 0; m < 64; m++) {
        int n = nb + m;
        if (n < N_NODES) g_PdstH[(size_t)n * HID + j] = __float2half(acc[m]);
    }
#pragma unroll
    for (int m = 0; m < 64; m++) acc[m] = 0.f;
    for (int k = 0; k < F_DIM; k++) {
        float w = __ldg(W1 + (size_t)(160 + k) * HID + j);
        const float4* f4 = (const float4*)(fs + k * 68);
#pragma unroll
        for (int mq = 0; mq < 16; mq++) {
            float4 f = f4[mq];
            acc[4 * mq + 0] += f.x * w; acc[4 * mq + 1] += f.y * w;
            acc[4 * mq + 2] += f.z * w; acc[4 * mq + 3] += f.w * w;
        }
    }
    for (int m = 0; m < 64; m++) {
        int n = nb + m;
        if (n < N_NODES) g_PsrcH[(size_t)n * HID + j] = __float2half(acc[m]);
    }
}

// ---------------------------------------------------------------------------
// Kernel 2: fp16-convert + quad-reordered uint2 fragment-pack W2/W3.
// ---------------------------------------------------------------------------
__global__ void weight_prep_kernel(const float* __restrict__ W2, const float* __restrict__ W3) {
    int i = blockIdx.x * blockDim.x + threadIdx.x;
    if (i < 128 * 512) {
        int u = i & 511, R = i >> 9;
        int c = (u >> 4) * 16 + (u & 1) * 8 + ((u >> 1) & 7);
        int k0 = (R >> 2) * 16 + 2 * (R & 3);
        g_W2q[i] = make_uint2(
            pack2(W2[(size_t)k0 * HID + c], W2[(size_t)(k0 + 1) * HID + c]),
            pack2(W2[(size_t)(k0 + 8) * HID + c], W2[(size_t)(k0 + 9) * HID + c]));
    } else if (i < 128 * 512 + 128 * 256) {
        int q = i - 128 * 512;
        int u = q & 255, R = q >> 8;
        int c = (u >> 4) * 16 + (u & 1) * 8 + ((u >> 1) & 7);
        int k0 = (R >> 2) * 16 + 2 * (R & 3);
        g_W3q[q] = make_uint2(
            pack2(W3[(size_t)k0 * OUTD + c], W3[(size_t)(k0 + 1) * OUTD + c]),
            pack2(W3[(size_t)(k0 + 8) * OUTD + c], W3[(size_t)(k0 + 9) * OUTD + c]));
    }
}

// ---------------------------------------------------------------------------
// Kernel 3: fused layers 2+3, fp16 mma, ldmatrix A, uint4 B, k64 chunks,
// 2-buffer cp.async ring, one sync per chunk. 64 edges/block, 512 threads.
// ---------------------------------------------------------------------------
#define HS_STRW 260                 // words per hs row
#define HS_W   (64 * HS_STRW)       // 16640 words
#define BUF_W  16512                // 16 rows * 516 u2 * 2 words
#define B2S_W  (HS_W + 2 * BUF_W)   // 49664
#define B3S_W  (B2S_W + 512)
#define W1H_W  (B3S_W + 256)
#define SMEM_BYTES ((W1H_W + 256) * 4)  // 202752

// t = 0..7: W2 k64 chunk t; t = 8..15: W3 k64 chunk t-8. Buffer t%2.
__device__ __forceinline__ void prefetch_chunk(int t, uint32_t wtu, int tid) {
    if (t < 8) {
        const uint2* srcq = g_W2q + (size_t)t * 8192;  // 16 rows x 512 u2
        uint32_t dstu = wtu + (uint32_t)(t & 1) * (BUF_W * 4);
#pragma unroll
        for (int i = 0; i < 8; i++) {
            int idx = tid + i * 512;
            int wr = idx >> 8, c0 = (idx & 255) * 2;
            CP16(dstu + (uint32_t)(wr * 516 + c0) * 8, srcq + wr * 512 + c0);
        }
    } else if (t < 16) {
        const uint2* srcq = g_W3q + (size_t)(t - 8) * 4096;  // 16 rows x 256 u2
        uint32_t dstu = wtu + (uint32_t)(t & 1) * (BUF_W * 4);
#pragma unroll
        for (int i = 0; i < 4; i++) {
            int idx = tid + i * 512;
            int wr = idx >> 7, c0 = (idx & 127) * 2;
            CP16(dstu + (uint32_t)(wr * 260 + c0) * 8, srcq + wr * 256 + c0);
        }
    }
    CP_COMMIT();
}

__global__ __launch_bounds__(512, 1) void edge_mlp_kernel(
    const int* __restrict__ src_idx, const int* __restrict__ dst_idx,
    const float* __restrict__ distance, const float* __restrict__ W1,
    const float* __restrict__ b2, const float* __restrict__ b3,
    float* __restrict__ out) {
    extern __shared__ float sm[];
    uint32_t* smw = (uint32_t*)sm;
    float* b2s = sm + B2S_W;
    float* b3s = sm + B3S_W;
    uint32_t* w1h = smw + W1H_W;
    const uint32_t wtu = smem_u32(smw + HS_W);

    const int tid = threadIdx.x, lane = tid & 31, warp = tid >> 5;
    const int wm = warp >> 3;   // 0..1
    const int wn = warp & 7;    // 0..7
    const int g = lane >> 2, tg = lane & 3;
    const int ebase = blockIdx.x * 64;

    // ldmatrix lane address bases (A fragments for rows wm*32.. and +16)
    const int rowoff = ((lane >> 3) & 1) * 8 + (lane & 7);
    const int koff = (lane >> 4) * 4;
    const uint32_t a0base = smem_u32(smw) +
        (uint32_t)(((wm * 32 + rowoff) * HS_STRW + koff) * 4);
    const uint32_t a1base = a0base + 16 * HS_STRW * 4;

    b2s[tid & 511] = b2[tid & 511];
    if (tid < 256) {
        w1h[tid] = pack2(W1[(size_t)320 * HID + 2 * tid],
                         W1[(size_t)320 * HID + 2 * tid + 1]);
        b3s[tid] = b3[tid];
    }

    prefetch_chunk(0, wtu, tid);
    __syncthreads();  // publish w1h before staging reads it

    // ---- stage h1 = half(relu(PdstH[dst] + PsrcH[src] + dist*W1[320])) ----
    {
        const int m = tid >> 3, q = tid & 7;
        const int e = ebase + m;
        const int dI = dst_idx[e], sI = src_idx[e];
        const __half2 d2 = __float2half2_rn(distance[e]);
        const uint4* pd = (const uint4*)(g_PdstH + (size_t)dI * HID);
        const uint4* ps = (const uint4*)(g_PsrcH + (size_t)sI * HID);
        uint32_t* hrow = smw + m * HS_STRW;
#pragma unroll
        for (int t = 0; t < 8; t++) {
            int u = t * 8 + q;
            uint4 A = __ldg(pd + u);
            uint4 B = __ldg(ps + u);
            uint4 W = *(const uint4*)(w1h + u * 4);
            uint4 o;
            o.x = h1op(A.x, B.x, W.x, d2);
            o.y = h1op(A.y, B.y, W.y, d2);
            o.z = h1op(A.z, B.z, W.z, d2);
            o.w = h1op(A.w, B.w, W.w, d2);
            *(uint4*)(hrow + u * 4) = o;
        }
    }

    // =================== Layer 2: 8 chunks of k=64 ==========================
    float acc[2][8][4];
#pragma unroll
    for (int mt = 0; mt < 2; mt++)
#pragma unroll
        for (int nt = 0; nt < 8; nt++)
#pragma unroll
            for (int i = 0; i < 4; i++) acc[mt][nt][i] = 0.f;

    for (int t = 0; t < 8; t++) {
        CP_WAIT0();          // chunk t resident
        __syncthreads();     // all warps done with buffer (t+1)&1
        prefetch_chunk(t + 1, wtu, tid);
        const uint2* bufu2 = (const uint2*)(smw + HS_W + (t & 1) * BUF_W);
#pragma unroll
        for (int s = 0; s < 4; s++) {
            const int kw = t * 32 + s * 8;
            uint32_t a0[4], a1[4];
            LDSM4(a0, a0base + kw * 4);
            LDSM4(a1, a1base + kw * 4);
            const uint4* wrow4 = (const uint4*)(bufu2 + (s * 4 + tg) * 516);
#pragma unroll
            for (int bp = 0; bp < 4; bp++) {
                uint4 B = wrow4[(wn * 4 + bp) * 8 + g];
                mma16(acc[0][2 * bp],     a0, B.x, B.y);
                mma16(acc[1][2 * bp],     a1, B.x, B.y);
                mma16(acc[0][2 * bp + 1], a0, B.z, B.w);
                mma16(acc[1][2 * bp + 1], a1, B.z, B.w);
            }
        }
    }
    __syncthreads();  // all hs (layer-2 A) reads done before overwrite

    // ---- epilogue 2: h2 = half(relu(acc + b2)) back into hs ----
#pragma unroll
    for (int mt = 0; mt < 2; mt++)
#pragma unroll
        for (int nt = 0; nt < 8; nt++) {
            int r = wm * 32 + mt * 16 + g;
            int cw = wn * 32 + nt * 4 + tg;
            int c = 2 * cw;
            float ba = b2s[c], bb = b2s[c + 1];
            smw[r * HS_STRW + cw] = pack2(fmaxf(acc[mt][nt][0] + ba, 0.f),
                                          fmaxf(acc[mt][nt][1] + bb, 0.f));
            smw[(r + 8) * HS_STRW + cw] = pack2(fmaxf(acc[mt][nt][2] + ba, 0.f),
                                                fmaxf(acc[mt][nt][3] + bb, 0.f));
        }

    // =================== Layer 3: 8 chunks of k=64 ==========================
    float acc3[2][4][4];
#pragma unroll
    for (int mt = 0; mt < 2; mt++)
#pragma unroll
        for (int nt = 0; nt < 4; nt++)
#pragma unroll
            for (int i = 0; i < 4; i++) acc3[mt][nt][i] = 0.f;

    for (int q = 0; q < 8; q++) {
        CP_WAIT0();
        __syncthreads();  // q==0 also publishes epilogue-2 hs writes
        prefetch_chunk(9 + q, wtu, tid);
        const uint2* bufu2 = (const uint2*)(smw + HS_W + (q & 1) * BUF_W);
#pragma unroll
        for (int s = 0; s < 4; s++) {
            const int kw = q * 32 + s * 8;
            uint32_t a0[4], a1[4];
            LDSM4(a0, a0base + kw * 4);
            LDSM4(a1, a1base + kw * 4);
            const uint4* wrow4 = (const uint4*)(bufu2 + (s * 4 + tg) * 260);
#pragma unroll
            for (int bp = 0; bp < 2; bp++) {
                uint4 B = wrow4[(wn * 2 + bp) * 8 + g];
                mma16(acc3[0][2 * bp],     a0, B.x, B.y);
                mma16(acc3[1][2 * bp],     a1, B.x, B.y);
                mma16(acc3[0][2 * bp + 1], a0, B.z, B.w);
                mma16(acc3[1][2 * bp + 1], a1, B.z, B.w);
            }
        }
    }

    // ---- epilogue 3: out = acc3 + b3 (fp32) ----
#pragma unroll
    for (int mt = 0; mt < 2; mt++)
#pragma unroll
        for (int nt = 0; nt < 4; nt++) {
            int r = wm * 32 + mt * 16 + g;
            int c = wn * 32 + nt * 8 + tg * 2;
            size_t row0 = (size_t)(ebase + r) * OUTD;
            size_t row8 = (size_t)(ebase + r + 8) * OUTD;
            float ba = b3s[c], bb = b3s[c + 1];
            out[row0 + c]     = acc3[mt][nt][0] + ba;
            out[row0 + c + 1] = acc3[mt][nt][1] + bb;
            out[row8 + c]     = acc3[mt][nt][2] + ba;
            out[row8 + c + 1] = acc3[mt][nt][3] + bb;
        }
}

// -----------------------------------------------------------------------------
extern "C" void kernel_launch(void* const* d_in, const int* in_sizes, int n_in,
                              void* d_out, int out_size) {
    const float* nf   = (const float*)d_in[0];
    const float* nh   = (const float*)d_in[1];
    const int*   src  = (const int*)d_in[2];
    const int*   dst  = (const int*)d_in[3];
    const float* dist = (const float*)d_in[4];
    const float* W1   = (const float*)d_in[5];
    const float* b1   = (const float*)d_in[6];
    const float* W2   = (const float*)d_in[7];
    const float* b2   = (const float*)d_in[8];
    const float* W3   = (const float*)d_in[9];
    const float* b3   = (const float*)d_in[10];
    float* out = (float*)d_out;

    static bool attr_set = false;
    if (!attr_set) {
        cudaFuncSetAttribute(edge_mlp_kernel,
                             cudaFuncAttributeMaxDynamicSharedMemorySize, SMEM_BYTES);
        attr_set = true;
    }
    node_pre_kernel<<<(N_NODES + 63) / 64, 512>>>(nf, nh, W1, b1);
    weight_prep_kernel<<<(128 * 512 + 128 * 256 + 255) / 256, 256>>>(W2, W3);
    edge_mlp_kernel<<<N_EDGES / 64, 512, SMEM_BYTES>>>(src, dst, dist, W1, b2, b3, out);
}

// round 12
// speedup vs baseline: 1.3474x; 1.3474x over previous
#include <cuda_runtime.h>
#include <cuda_fp16.h>
#include <cstdint>

#define N_NODES 50000
#define N_EDGES 1600000
#define F_DIM 32
#define H_DIM 128
#define HID 512
#define OUTD 256

// Scratch (__device__ globals = allocation-guard-legal scratch)
__device__ __align__(16) __half g_PdstH[(size_t)N_NODES * HID];
__device__ __align__(16) __half g_PsrcH[(size_t)N_NODES * HID];
// fp16 weights, B-fragment u2 {(k0,k0+1),(k0+8,k0+9)} with quad-reordered cols:
// row R (0..127): slice=R>>2, tg=R&3, k0=slice*16+2*tg.
// u2 index u in row: c = (u>>4)*16 + (u&1)*8 + ((u>>1)&7)
// => uint4 slot q holds cols {(q>>3)*16+(q&7), +8} (verified in R10, rel_err identical).
__device__ __align__(16) uint2 g_W2q[(size_t)128 * 512];
__device__ __align__(16) uint2 g_W3q[(size_t)128 * 256];

__device__ __forceinline__ uint32_t smem_u32(const void* p) {
    uint32_t a;
    asm("{ .reg .u64 t; cvta.to.shared.u64 t, %1; cvt.u32.u64 %0, t; }" : "=r"(a) : "l"(p));
    return a;
}
__device__ __forceinline__ void mma16(float* d, const uint32_t* a,
                                      uint32_t b0, uint32_t b1) {
    asm volatile(
        "mma.sync.aligned.m16n8k16.row.col.f32.f16.f16.f32 "
        "{%0,%1,%2,%3},{%4,%5,%6,%7},{%8,%9},{%0,%1,%2,%3};"
        : "+f"(d[0]), "+f"(d[1]), "+f"(d[2]), "+f"(d[3])
        : "r"(a[0]), "r"(a[1]), "r"(a[2]), "r"(a[3]), "r"(b0), "r"(b1));
}
#define LDSM4(r, addr) \
    asm volatile("ldmatrix.sync.aligned.m8n8.x4.shared.b16 {%0,%1,%2,%3}, [%4];" \
        : "=r"((r)[0]), "=r"((r)[1]), "=r"((r)[2]), "=r"((r)[3]) : "r"(addr))
__device__ __forceinline__ uint32_t pack2(float x, float y) {
    __half2 h = __floats2half2_rn(x, y);
    return *(uint32_t*)&h;
}
__device__ __forceinline__ uint32_t h1op(uint32_t a, uint32_t b, uint32_t w,
                                         __half2 d2) {
    __half2 r = __hfma2(d2, *(__half2*)&w,
                        __hadd2(*(__half2*)&a, *(__half2*)&b));
    r = __hmax2(r, __floats2half2_rn(0.f, 0.f));
    return *(uint32_t*)&r;
}
#define CP16(sa, gp) asm volatile("cp.async.cg.shared.global [%0], [%1], 16;" :: "r"(sa), "l"(gp) : "memory")
#define CP_COMMIT() asm volatile("cp.async.commit_group;" ::: "memory")
#define CP_WAIT1()  asm volatile("cp.async.wait_group 1;" ::: "memory")

// ---------------------------------------------------------------------------
// Kernel 1: per-node layer-1 precompute. 256-thread blocks (2 per node tile,
// 256 output cols each) -> 2 CTAs/SM for latency hiding.
// ---------------------------------------------------------------------------
__global__ __launch_bounds__(256) void node_pre_kernel(
    const float* __restrict__ nf, const float* __restrict__ nh,
    const float* __restrict__ W1, const float* __restrict__ b1) {
    __shared__ float fs[160 * 68];  // fs[k][m]
    const int nb = (blockIdx.x >> 1) * 64, tid = threadIdx.x;
    const int j = (blockIdx.x & 1) * 256 + tid;
    for (int idx = tid; idx < 64 * 160; idx += 256) {
        int k = idx >> 6, m = idx & 63, n = nb + m;
        float v = 0.f;
        if (n < N_NODES)
            v = (k < F_DIM) ? nf[(size_t)n * F_DIM + k] : nh[(size_t)n * H_DIM + (k - F_DIM)];
        fs[k * 68 + m] = v;
    }
    __syncthreads();
    float acc[64];
    const float bj = b1[j];
#pragma unroll
    for (int m = 0; m < 64; m++) acc[m] = bj;
    for (int k = 0; k < F_DIM; k++) {
        float w = __ldg(W1 + (size_t)k * HID + j);
        const float4* f4 = (const float4*)(fs + k * 68);
#pragma unroll
        for (int mq = 0; mq < 16; mq++) {
            float4 f = f4[mq];
            acc[4 * mq + 0] += f.x * w; acc[4 * mq + 1] += f.y * w;
            acc[4 * mq + 2] += f.z * w; acc[4 * mq + 3] += f.w * w;
        }
    }
    for (int h = 0; h < H_DIM; h++) {
        float w = __ldg(W1 + (size_t)(32 + h) * HID + j) +
                  __ldg(W1 + (size_t)(192 + h) * HID + j);
        const float4* f4 = (const float4*)(fs + (32 + h) * 68);
#pragma unroll
        for (int mq = 0; mq < 16; mq++) {
            float4 f = f4[mq];
            acc[4 * mq + 0] += f.x * w; acc[4 * mq + 1] += f.y * w;
            acc[4 * mq + 2] += f.z * w; acc[4 * mq + 3] += f.w * w;
        }
    }
    for (int m = 0; m < 64; m++) {
        int n = nb + m;
        if (n < N_NODES) g_PdstH[(size_t)n * HID + j] = __float2half(acc[m]);
    }
#pragma unroll
    for (int m = 0; m < 64; m++) acc[m] = 0.f;
    for (int k = 0; k < F_DIM; k++) {
        float w = __ldg(W1 + (size_t)(160 + k) * HID + j);
        const float4* f4 = (const float4*)(fs + k * 68);
#pragma unroll
        for (int mq = 0; mq < 16; mq++) {
            float4 f = f4[mq];
            acc[4 * mq + 0] += f.x * w; acc[4 * mq + 1] += f.y * w;
            acc[4 * mq + 2] += f.z * w; acc[4 * mq + 3] += f.w * w;
        }
    }
    for (int m = 0; m < 64; m++) {
        int n = nb + m;
        if (n < N_NODES) g_PsrcH[(size_t)n * HID + j] = __float2half(acc[m]);
    }
}

// ---------------------------------------------------------------------------
// Kernel 2: fp16-convert + quad-reordered uint2 fragment-pack W2/W3.
// ---------------------------------------------------------------------------
__global__ void weight_prep_kernel(const float* __restrict__ W2, const float* __restrict__ W3) {
    int i = blockIdx.x * blockDim.x + threadIdx.x;
    if (i < 128 * 512) {
        int u = i & 511, R = i >> 9;
        int c = (u >> 4) * 16 + (u & 1) * 8 + ((u >> 1) & 7);
        int k0 = (R >> 2) * 16 + 2 * (R & 3);
        g_W2q[i] = make_uint2(
            pack2(W2[(size_t)k0 * HID + c], W2[(size_t)(k0 + 1) * HID + c]),
            pack2(W2[(size_t)(k0 + 8) * HID + c], W2[(size_t)(k0 + 9) * HID + c]));
    } else if (i < 128 * 512 + 128 * 256) {
        int q = i - 128 * 512;
        int u = q & 255, R = q >> 8;
        int c = (u >> 4) * 16 + (u & 1) * 8 + ((u >> 1) & 7);
        int k0 = (R >> 2) * 16 + 2 * (R & 3);
        g_W3q[q] = make_uint2(
            pack2(W3[(size_t)k0 * OUTD + c], W3[(size_t)(k0 + 1) * OUTD + c]),
            pack2(W3[(size_t)(k0 + 8) * OUTD + c], W3[(size_t)(k0 + 9) * OUTD + c]));
    }
}

// ---------------------------------------------------------------------------
// Kernel 3: fused layers 2+3. R9 pipeline (k32 chunks, 3-buffer ring,
// wait_group 1 = 2 chunks in flight) + ldmatrix A + uint4 B.
// 64 edges/block, 512 threads = 16 warps (2m x 8n).
// ---------------------------------------------------------------------------
#define HS_STRW 260                 // words per hs row
#define HS_W   (64 * HS_STRW)       // 16640 words
#define BUF_W  8256                 // 8 rows * 516 u2 * 2 words (W2 k32 chunk)
#define B2S_W  (HS_W + 3 * BUF_W)   // 41408
#define B3S_W  (B2S_W + 512)
#define W1H_W  (B3S_W + 256)
#define SMEM_BYTES ((W1H_W + 256) * 4)  // 169728

// t = 0..15: W2 k32 chunk t; t = 16..31: W3 k32 chunk t-16. Buffer t%3.
__device__ __forceinline__ void prefetch_chunk(int t, uint32_t wtu, int tid) {
    if (t < 16) {
        const uint2* srcq = g_W2q + (size_t)t * 4096;  // 8 rows x 512 u2
        uint32_t dstu = wtu + (uint32_t)(t % 3) * (BUF_W * 4);
#pragma unroll
        for (int i = 0; i < 4; i++) {
            int idx = tid + i * 512;
            int wr = idx >> 8, c0 = (idx & 255) * 2;
            CP16(dstu + (uint32_t)(wr * 516 + c0) * 8, srcq + wr * 512 + c0);
        }
    } else if (t < 32) {
        const uint2* srcq = g_W3q + (size_t)(t - 16) * 2048;  // 8 rows x 256 u2
        uint32_t dstu = wtu + (uint32_t)(t % 3) * (BUF_W * 4);
#pragma unroll
        for (int i = 0; i < 2; i++) {
            int idx = tid + i * 512;
            int wr = idx >> 7, c0 = (idx & 127) * 2;
            CP16(dstu + (uint32_t)(wr * 260 + c0) * 8, srcq + wr * 256 + c0);
        }
    }
    CP_COMMIT();  // empty group for t>=32 keeps wait_group arithmetic uniform
}

__global__ __launch_bounds__(512, 1) void edge_mlp_kernel(
    const int* __restrict__ src_idx, const int* __restrict__ dst_idx,
    const float* __restrict__ distance, const float* __restrict__ W1,
    const float* __restrict__ b2, const float* __restrict__ b3,
    float* __restrict__ out) {
    extern __shared__ float sm[];
    uint32_t* smw = (uint32_t*)sm;
    float* b2s = sm + B2S_W;
    float* b3s = sm + B3S_W;
    uint32_t* w1h = smw + W1H_W;
    const uint32_t wtu = smem_u32(smw + HS_W);

    const int tid = threadIdx.x, lane = tid & 31, warp = tid >> 5;
    const int wm = warp >> 3;   // 0..1
    const int wn = warp & 7;    // 0..7
    const int g = lane >> 2, tg = lane & 3;
    const int ebase = blockIdx.x * 64;

    // ldmatrix lane address bases (verified mapping, R10)
    const int rowoff = ((lane >> 3) & 1) * 8 + (lane & 7);
    const int koff = (lane >> 4) * 4;
    const uint32_t a0base = smem_u32(smw) +
        (uint32_t)(((wm * 32 + rowoff) * HS_STRW + koff) * 4);
    const uint32_t a1base = a0base + 16 * HS_STRW * 4;

    b2s[tid & 511] = b2[tid & 511];
    if (tid < 256) {
        w1h[tid] = pack2(W1[(size_t)320 * HID + 2 * tid],
                         W1[(size_t)320 * HID + 2 * tid + 1]);
        b3s[tid] = b3[tid];
    }

    prefetch_chunk(0, wtu, tid);
    prefetch_chunk(1, wtu, tid);
    __syncthreads();  // publish w1h before staging reads it

    // ---- stage h1 = half(relu(PdstH[dst] + PsrcH[src] + dist*W1[320])) ----
    {
        const int m = tid >> 3, q = tid & 7;
        const int e = ebase + m;
        const int dI = dst_idx[e], sI = src_idx[e];
        const __half2 d2 = __float2half2_rn(distance[e]);
        const uint4* pd = (const uint4*)(g_PdstH + (size_t)dI * HID);
        const uint4* ps = (const uint4*)(g_PsrcH + (size_t)sI * HID);
        uint32_t* hrow = smw + m * HS_STRW;
#pragma unroll
        for (int t = 0; t < 8; t++) {
            int u = t * 8 + q;
            uint4 A = __ldg(pd + u);
            uint4 B = __ldg(ps + u);
            uint4 W = *(const uint4*)(w1h + u * 4);
            uint4 o;
            o.x = h1op(A.x, B.x, W.x, d2);
            o.y = h1op(A.y, B.y, W.y, d2);
            o.z = h1op(A.z, B.z, W.z, d2);
            o.w = h1op(A.w, B.w, W.w, d2);
            *(uint4*)(hrow + u * 4) = o;
        }
    }

    // =================== Layer 2: 16 chunks of k=32 =========================
    float acc[2][8][4];
#pragma unroll
    for (int mt = 0; mt < 2; mt++)
#pragma unroll
        for (int nt = 0; nt < 8; nt++)
#pragma unroll
            for (int i = 0; i < 4; i++) acc[mt][nt][i] = 0.f;

    for (int cc = 0; cc < 16; cc++) {
        CP_WAIT1();          // chunk cc resident (cc+1 still in flight)
        __syncthreads();     // all warps done with buffer (cc-1)%3
        prefetch_chunk(cc + 2, wtu, tid);
        const uint2* bufu2 = (const uint2*)(smw + HS_W + (cc % 3) * BUF_W);
#pragma unroll
        for (int s = 0; s < 2; s++) {
            const int kw = cc * 16 + s * 8;
            uint32_t a0[4], a1[4];
            LDSM4(a0, a0base + kw * 4);
            LDSM4(a1, a1base + kw * 4);
            const uint4* wrow4 = (const uint4*)(bufu2 + (s * 4 + tg) * 516);
#pragma unroll
            for (int bp = 0; bp < 4; bp++) {
                uint4 B = wrow4[(wn * 4 + bp) * 8 + g];
                mma16(acc[0][2 * bp],     a0, B.x, B.y);
                mma16(acc[1][2 * bp],     a1, B.x, B.y);
                mma16(acc[0][2 * bp + 1], a0, B.z, B.w);
                mma16(acc[1][2 * bp + 1], a1, B.z, B.w);
            }
        }
    }
    __syncthreads();  // all hs (layer-2 A) reads done before overwrite

    // ---- epilogue 2: h2 = half(relu(acc + b2)) back into hs ----
    // acc[mt][2*bp+p] covers cols c = (wn*4+bp)*16 + p*8 + 2tg (+1)
#pragma unroll
    for (int mt = 0; mt < 2; mt++)
#pragma unroll
        for (int nt = 0; nt < 8; nt++) {
            int r = wm * 32 + mt * 16 + g;
            int bp = nt >> 1, p = nt & 1;
            int c = (wn * 4 + bp) * 16 + p * 8 + tg * 2;
            int cw = c >> 1;
            float ba = b2s[c], bb = b2s[c + 1];
            smw[r * HS_STRW + cw] = pack2(fmaxf(acc[mt][nt][0] + ba, 0.f),
                                          fmaxf(acc[mt][nt][1] + bb, 0.f));
            smw[(r + 8) * HS_STRW + cw] = pack2(fmaxf(acc[mt][nt][2] + ba, 0.f),
                                                fmaxf(acc[mt][nt][3] + bb, 0.f));
        }

    // =================== Layer 3: 16 chunks of k=32 =========================
    float acc3[2][4][4];
#pragma unroll
    for (int mt = 0; mt < 2; mt++)
#pragma unroll
        for (int nt = 0; nt < 4; nt++)
#pragma unroll
            for (int i = 0; i < 4; i++) acc3[mt][nt][i] = 0.f;

    for (int g3 = 0; g3 < 16; g3++) {
        CP_WAIT1();
        __syncthreads();  // g3==0 also publishes epilogue-2 hs writes
        prefetch_chunk(18 + g3, wtu, tid);
        const uint2* bufu2 = (const uint2*)(smw + HS_W + ((16 + g3) % 3) * BUF_W);
#pragma unroll
        for (int s = 0; s < 2; s++) {
            const int kw = g3 * 16 + s * 8;
            uint32_t a0[4], a1[4];
            LDSM4(a0, a0base + kw * 4);
            LDSM4(a1, a1base + kw * 4);
            const uint4* wrow4 = (const uint4*)(bufu2 + (s * 4 + tg) * 260);
#pragma unroll
            for (int bp = 0; bp < 2; bp++) {
                uint4 B = wrow4[(wn * 2 + bp) * 8 + g];
                mma16(acc3[0][2 * bp],     a0, B.x, B.y);
                mma16(acc3[1][2 * bp],     a1, B.x, B.y);
                mma16(acc3[0][2 * bp + 1], a0, B.z, B.w);
                mma16(acc3[1][2 * bp + 1], a1, B.z, B.w);
            }
        }
    }

    // ---- epilogue 3: out = acc3 + b3 (fp32) ----
    // acc3[mt][2*bp+p] covers cols c = (wn*2+bp)*16 + p*8 + 2tg (+1)
#pragma unroll
    for (int mt = 0; mt < 2; mt++)
#pragma unroll
        for (int nt = 0; nt < 4; nt++) {
            int r = wm * 32 + mt * 16 + g;
            int bp = nt >> 1, p = nt & 1;
            int c = (wn * 2 + bp) * 16 + p * 8 + tg * 2;
            size_t row0 = (size_t)(ebase + r) * OUTD;
            size_t row8 = (size_t)(ebase + r + 8) * OUTD;
            float ba = b3s[c], bb = b3s[c + 1];
            out[row0 + c]     = acc3[mt][nt][0] + ba;
            out[row0 + c + 1] = acc3[mt][nt][1] + bb;
            out[row8 + c]     = acc3[mt][nt][2] + ba;
            out[row8 + c + 1] = acc3[mt][nt][3] + bb;
        }
}

// -----------------------------------------------------------------------------
extern "C" void kernel_launch(void* const* d_in, const int* in_sizes, int n_in,
                              void* d_out, int out_size) {
    const float* nf   = (const float*)d_in[0];
    const float* nh   = (const float*)d_in[1];
    const int*   src  = (const int*)d_in[2];
    const int*   dst  = (const int*)d_in[3];
    const float* dist = (const float*)d_in[4];
    const float* W1   = (const float*)d_in[5];
    const float* b1   = (const float*)d_in[6];
    const float* W2   = (const float*)d_in[7];
    const float* b2   = (const float*)d_in[8];
    const float* W3   = (const float*)d_in[9];
    const float* b3   = (const float*)d_in[10];
    float* out = (float*)d_out;

    static bool attr_set = false;
    if (!attr_set) {
        cudaFuncSetAttribute(edge_mlp_kernel,
                             cudaFuncAttributeMaxDynamicSharedMemorySize, SMEM_BYTES);
        attr_set = true;
    }
    node_pre_kernel<<<2 * ((N_NODES + 63) / 64), 256>>>(nf, nh, W1, b1);
    weight_prep_kernel<<<(128 * 512 + 128 * 256 + 255) / 256, 256>>>(W2, W3);
    edge_mlp_kernel<<<N_EDGES / 64, 512, SMEM_BYTES>>>(src, dst, dist, W1, b2, b3, out);
}